// round 6
// baseline (speedup 1.0000x reference)
#include <cuda_runtime.h>

#define N_NODES 100000
#define N_EDGES 3200000
#define N_GRAPHS 64
#define IN_CH 64
#define HID 128
#define LAT 32
#define EPS 1e-5f

// ---------------- scratch (static device allocations; no runtime allocs) ----------------
__device__ __align__(16) float g_h1[(size_t)N_NODES * HID];   // x @ W1
__device__ __align__(16) float g_a1[(size_t)N_NODES * HID];   // agg1 + bn + relu
__device__ __align__(16) float g_z [(size_t)N_NODES * LAT];   // a1 @ W2
__device__ __align__(16) float g_zn[(size_t)N_NODES * LAT];   // agg2 + bn + relu (z_nodes)
__device__ __align__(16) float g_d [(size_t)N_NODES * HID];   // decoder hidden
__device__ float g_dis[N_NODES];
__device__ int   g_deg[N_NODES];
__device__ int   g_off[N_NODES + 1];
__device__ int   g_cnt[N_NODES];
__device__ int   g_rows[N_EDGES];
__device__ float g_zsum[N_GRAPHS * LAT];
__device__ int   g_gcnt[N_GRAPHS];

// ---------------- setup kernels ----------------
__global__ void k_zero() {
    int i = blockIdx.x * blockDim.x + threadIdx.x;
    if (i < N_NODES) { g_deg[i] = 0; g_cnt[i] = 0; }
    if (i < N_GRAPHS * LAT) g_zsum[i] = 0.f;
    if (i < N_GRAPHS) g_gcnt[i] = 0;
}

__global__ void k_deg(const int* __restrict__ ei) {
    int e = blockIdx.x * blockDim.x + threadIdx.x;
    if (e < N_EDGES) {
        int c = ei[N_EDGES + e];
        atomicAdd(&g_deg[c], 1);
    }
}

__global__ void k_dis() {
    int i = blockIdx.x * blockDim.x + threadIdx.x;
    if (i < N_NODES) {
        int d = g_deg[i];
        g_dis[i] = (d > 0) ? rsqrtf((float)d) : 0.f;
    }
}

// single-block exclusive scan of g_deg -> g_off
__global__ void k_scan() {
    __shared__ int ss[1024];
    int tid = threadIdx.x;
    const int CH = (N_NODES + 1023) / 1024;
    int b = tid * CH;
    int e = b + CH; if (e > N_NODES) e = N_NODES;
    if (b > N_NODES) b = N_NODES;
    int s = 0;
    for (int i = b; i < e; i++) s += g_deg[i];
    ss[tid] = s;
    __syncthreads();
    for (int off = 1; off < 1024; off <<= 1) {
        int v = (tid >= off) ? ss[tid - off] : 0;
        __syncthreads();
        ss[tid] += v;
        __syncthreads();
    }
    int run = (tid > 0) ? ss[tid - 1] : 0;
    for (int i = b; i < e; i++) { g_off[i] = run; run += g_deg[i]; }
    if (tid == 1023) g_off[N_NODES] = ss[1023];
}

__global__ void k_fill(const int* __restrict__ ei) {
    int e = blockIdx.x * blockDim.x + threadIdx.x;
    if (e < N_EDGES) {
        int r = ei[e];
        int c = ei[N_EDGES + e];
        int pos = g_off[c] + atomicAdd(&g_cnt[c], 1);
        g_rows[pos] = r;
    }
}

// ---------------- GEMM1: h1 = x[N,64] @ W1[64,128] (warp per node) ----------------
__global__ void k_gemm1(const float* __restrict__ x, const float* __restrict__ w) {
    int warp = (blockIdx.x * blockDim.x + threadIdx.x) >> 5;
    int lane = threadIdx.x & 31;
    if (warp >= N_NODES) return;
    float x0 = x[warp * 64 + lane];
    float x1 = x[warp * 64 + 32 + lane];
    const float4* __restrict__ w4 = (const float4*)w;
    float4 acc = make_float4(0.f, 0.f, 0.f, 0.f);
#pragma unroll 8
    for (int k = 0; k < 32; k++) {
        float xk = __shfl_sync(0xffffffffu, x0, k);
        float4 wv = w4[k * 32 + lane];
        acc.x += xk * wv.x; acc.y += xk * wv.y; acc.z += xk * wv.z; acc.w += xk * wv.w;
    }
#pragma unroll 8
    for (int k = 0; k < 32; k++) {
        float xk = __shfl_sync(0xffffffffu, x1, k);
        float4 wv = w4[(k + 32) * 32 + lane];
        acc.x += xk * wv.x; acc.y += xk * wv.y; acc.z += xk * wv.z; acc.w += xk * wv.w;
    }
    ((float4*)g_h1)[warp * 32 + lane] = acc;
}

// ---------------- agg1: warp per node, 128ch (float4/thread), + bias + bn1 + relu ----------------
__global__ void k_agg1(const float* __restrict__ cb,
                       const float* __restrict__ bg, const float* __restrict__ bb,
                       const float* __restrict__ bm, const float* __restrict__ bv) {
    int node = (blockIdx.x * blockDim.x + threadIdx.x) >> 5;
    int lane = threadIdx.x & 31;
    if (node >= N_NODES) return;
    int s = g_off[node], e = g_off[node + 1];
    const float4* __restrict__ h4 = (const float4*)g_h1;
    float4 acc = make_float4(0.f, 0.f, 0.f, 0.f);
    int i = s;
    for (; i + 3 < e; i += 4) {
        int r0 = g_rows[i], r1 = g_rows[i + 1], r2 = g_rows[i + 2], r3 = g_rows[i + 3];
        float w0 = g_dis[r0], w1 = g_dis[r1], w2 = g_dis[r2], w3 = g_dis[r3];
        float4 v0 = h4[r0 * 32 + lane];
        float4 v1 = h4[r1 * 32 + lane];
        float4 v2 = h4[r2 * 32 + lane];
        float4 v3 = h4[r3 * 32 + lane];
        acc.x += v0.x * w0 + v1.x * w1 + v2.x * w2 + v3.x * w3;
        acc.y += v0.y * w0 + v1.y * w1 + v2.y * w2 + v3.y * w3;
        acc.z += v0.z * w0 + v1.z * w1 + v2.z * w2 + v3.z * w3;
        acc.w += v0.w * w0 + v1.w * w1 + v2.w * w2 + v3.w * w3;
    }
    for (; i < e; i++) {
        int r = g_rows[i];
        float w = g_dis[r];
        float4 v = h4[r * 32 + lane];
        acc.x += v.x * w; acc.y += v.y * w; acc.z += v.z * w; acc.w += v.w * w;
    }
    float dc = g_dis[node];
    int c0 = lane * 4;
    float4 o;
    {
        float v0 = acc.x * dc + cb[c0 + 0];
        float v1 = acc.y * dc + cb[c0 + 1];
        float v2 = acc.z * dc + cb[c0 + 2];
        float v3 = acc.w * dc + cb[c0 + 3];
        v0 = (v0 - bm[c0 + 0]) * bg[c0 + 0] * rsqrtf(bv[c0 + 0] + EPS) + bb[c0 + 0];
        v1 = (v1 - bm[c0 + 1]) * bg[c0 + 1] * rsqrtf(bv[c0 + 1] + EPS) + bb[c0 + 1];
        v2 = (v2 - bm[c0 + 2]) * bg[c0 + 2] * rsqrtf(bv[c0 + 2] + EPS) + bb[c0 + 2];
        v3 = (v3 - bm[c0 + 3]) * bg[c0 + 3] * rsqrtf(bv[c0 + 3] + EPS) + bb[c0 + 3];
        o = make_float4(fmaxf(v0, 0.f), fmaxf(v1, 0.f), fmaxf(v2, 0.f), fmaxf(v3, 0.f));
    }
    ((float4*)g_a1)[node * 32 + lane] = o;
}

// ---------------- GEMM2: z = a1[N,128] @ W2[128,32] (warp per 4 nodes) ----------------
__global__ void k_gemm2(const float* __restrict__ w) {
    int warp = (blockIdx.x * blockDim.x + threadIdx.x) >> 5;
    int lane = threadIdx.x & 31;
    int n0 = warp * 4;
    if (n0 >= N_NODES) return;
    float xv[4][4];
#pragma unroll
    for (int j = 0; j < 4; j++)
#pragma unroll
        for (int q = 0; q < 4; q++)
            xv[j][q] = g_a1[(n0 + j) * 128 + q * 32 + lane];
    float acc[4] = {0.f, 0.f, 0.f, 0.f};
#pragma unroll
    for (int q = 0; q < 4; q++) {
#pragma unroll 8
        for (int k = 0; k < 32; k++) {
            float wv = w[(q * 32 + k) * 32 + lane];
            float a0 = __shfl_sync(0xffffffffu, xv[0][q], k);
            float a1 = __shfl_sync(0xffffffffu, xv[1][q], k);
            float a2 = __shfl_sync(0xffffffffu, xv[2][q], k);
            float a3 = __shfl_sync(0xffffffffu, xv[3][q], k);
            acc[0] += a0 * wv; acc[1] += a1 * wv; acc[2] += a2 * wv; acc[3] += a3 * wv;
        }
    }
#pragma unroll
    for (int j = 0; j < 4; j++)
        g_z[(n0 + j) * 32 + lane] = acc[j];
}

// ---------------- agg2: warp per node, 32ch, + bias + bn2 + relu -> z_nodes ----------------
__global__ void k_agg2(const float* __restrict__ cb,
                       const float* __restrict__ bg, const float* __restrict__ bb,
                       const float* __restrict__ bm, const float* __restrict__ bv) {
    int node = (blockIdx.x * blockDim.x + threadIdx.x) >> 5;
    int lane = threadIdx.x & 31;
    if (node >= N_NODES) return;
    int s = g_off[node], e = g_off[node + 1];
    float acc = 0.f;
    int i = s;
    for (; i + 3 < e; i += 4) {
        int r0 = g_rows[i], r1 = g_rows[i + 1], r2 = g_rows[i + 2], r3 = g_rows[i + 3];
        float w0 = g_dis[r0], w1 = g_dis[r1], w2 = g_dis[r2], w3 = g_dis[r3];
        acc += g_z[r0 * 32 + lane] * w0 + g_z[r1 * 32 + lane] * w1
             + g_z[r2 * 32 + lane] * w2 + g_z[r3 * 32 + lane] * w3;
    }
    for (; i < e; i++) {
        int r = g_rows[i];
        acc += g_z[r * 32 + lane] * g_dis[r];
    }
    float v = acc * g_dis[node] + cb[lane];
    v = (v - bm[lane]) * bg[lane] * rsqrtf(bv[lane] + EPS) + bb[lane];
    g_zn[node * 32 + lane] = fmaxf(v, 0.f);
}

// ---------------- fc1: d = relu(bn(zn[N,32] @ fc1w[32,128] + b)) (warp per node) ----------------
__global__ void k_fc1(const float* __restrict__ w, const float* __restrict__ fb,
                      const float* __restrict__ bg, const float* __restrict__ bb,
                      const float* __restrict__ bm, const float* __restrict__ bv) {
    int node = (blockIdx.x * blockDim.x + threadIdx.x) >> 5;
    int lane = threadIdx.x & 31;
    if (node >= N_NODES) return;
    float xv = g_zn[node * 32 + lane];
    const float4* __restrict__ w4 = (const float4*)w;
    float4 acc = make_float4(0.f, 0.f, 0.f, 0.f);
#pragma unroll 8
    for (int k = 0; k < 32; k++) {
        float xk = __shfl_sync(0xffffffffu, xv, k);
        float4 wv = w4[k * 32 + lane];
        acc.x += xk * wv.x; acc.y += xk * wv.y; acc.z += xk * wv.z; acc.w += xk * wv.w;
    }
    int c0 = lane * 4;
    float v0 = acc.x + fb[c0 + 0];
    float v1 = acc.y + fb[c0 + 1];
    float v2 = acc.z + fb[c0 + 2];
    float v3 = acc.w + fb[c0 + 3];
    v0 = (v0 - bm[c0 + 0]) * bg[c0 + 0] * rsqrtf(bv[c0 + 0] + EPS) + bb[c0 + 0];
    v1 = (v1 - bm[c0 + 1]) * bg[c0 + 1] * rsqrtf(bv[c0 + 1] + EPS) + bb[c0 + 1];
    v2 = (v2 - bm[c0 + 2]) * bg[c0 + 2] * rsqrtf(bv[c0 + 2] + EPS) + bb[c0 + 2];
    v3 = (v3 - bm[c0 + 3]) * bg[c0 + 3] * rsqrtf(bv[c0 + 3] + EPS) + bb[c0 + 3];
    float4 o = make_float4(fmaxf(v0, 0.f), fmaxf(v1, 0.f), fmaxf(v2, 0.f), fmaxf(v3, 0.f));
    ((float4*)g_d)[node * 32 + lane] = o;
}

// ---------------- fc2: x_hat = d[N,128] @ fc2w[128,64] + b (warp per 2 nodes) -> d_out ----------------
__global__ void k_fc2(const float* __restrict__ w, const float* __restrict__ fb,
                      float* __restrict__ out) {
    int warp = (blockIdx.x * blockDim.x + threadIdx.x) >> 5;
    int lane = threadIdx.x & 31;
    int n0 = warp * 2;
    if (n0 >= N_NODES) return;
    float xv0[4], xv1[4];
#pragma unroll
    for (int q = 0; q < 4; q++) {
        xv0[q] = g_d[(size_t)n0 * 128 + q * 32 + lane];
        xv1[q] = g_d[(size_t)(n0 + 1) * 128 + q * 32 + lane];
    }
    const float2* __restrict__ w2 = (const float2*)w;
    float2 acc0 = make_float2(0.f, 0.f);
    float2 acc1 = make_float2(0.f, 0.f);
#pragma unroll
    for (int q = 0; q < 4; q++) {
#pragma unroll 8
        for (int k = 0; k < 32; k++) {
            float2 wv = w2[(q * 32 + k) * 32 + lane];
            float a = __shfl_sync(0xffffffffu, xv0[q], k);
            float b = __shfl_sync(0xffffffffu, xv1[q], k);
            acc0.x += a * wv.x; acc0.y += a * wv.y;
            acc1.x += b * wv.x; acc1.y += b * wv.y;
        }
    }
    int c0 = lane * 2;
    out[(size_t)n0 * 64 + c0 + 0] = acc0.x + fb[c0 + 0];
    out[(size_t)n0 * 64 + c0 + 1] = acc0.y + fb[c0 + 1];
    out[(size_t)(n0 + 1) * 64 + c0 + 0] = acc1.x + fb[c0 + 0];
    out[(size_t)(n0 + 1) * 64 + c0 + 1] = acc1.y + fb[c0 + 1];
}

// ---------------- pooling: smem per-block reduction over sorted batch ----------------
__global__ void k_pool(const int* __restrict__ batch) {
    __shared__ float sacc[N_GRAPHS * LAT];
    __shared__ int scnt[N_GRAPHS];
    int tid = threadIdx.x;
    for (int i = tid; i < N_GRAPHS * LAT; i += blockDim.x) sacc[i] = 0.f;
    if (tid < N_GRAPHS) scnt[tid] = 0;
    __syncthreads();
    const int NPB = 512;
    int base = blockIdx.x * NPB;
    int wid = tid >> 5, lane = tid & 31;
    int lim = base + NPB; if (lim > N_NODES) lim = N_NODES;
    for (int n = base + wid; n < lim; n += 8) {
        int g = batch[n];
        atomicAdd(&sacc[g * 32 + lane], g_zn[n * 32 + lane]);
        if (lane == 0) atomicAdd(&scnt[g], 1);
    }
    __syncthreads();
    for (int i = tid; i < N_GRAPHS * LAT; i += blockDim.x)
        if (sacc[i] != 0.f) atomicAdd(&g_zsum[i], sacc[i]);
    if (tid < N_GRAPHS && scnt[tid] != 0) atomicAdd(&g_gcnt[tid], scnt[tid]);
}

__global__ void k_fin(float* __restrict__ out) {
    int i = blockIdx.x * blockDim.x + threadIdx.x;
    if (i < N_GRAPHS * LAT) {
        int g = i >> 5;
        float c = (float)g_gcnt[g];
        out[(size_t)N_NODES * IN_CH + i] = g_zsum[i] / fmaxf(c, 1.f);
    }
}

// ---------------- launch ----------------
extern "C" void kernel_launch(void* const* d_in, const int* in_sizes, int n_in,
                              void* d_out, int out_size) {
    const float* x   = (const float*)d_in[0];
    const int*   ei  = (const int*)d_in[1];
    const int*   bat = (const int*)d_in[2];
    const float* c1w = (const float*)d_in[3];
    const float* c1b = (const float*)d_in[4];
    const float* c2w = (const float*)d_in[5];
    const float* c2b = (const float*)d_in[6];
    const float* bn1g = (const float*)d_in[7];
    const float* bn1b = (const float*)d_in[8];
    const float* bn1m = (const float*)d_in[9];
    const float* bn1v = (const float*)d_in[10];
    const float* bn2g = (const float*)d_in[11];
    const float* bn2b = (const float*)d_in[12];
    const float* bn2m = (const float*)d_in[13];
    const float* bn2v = (const float*)d_in[14];
    const float* f1w = (const float*)d_in[15];
    const float* f1b = (const float*)d_in[16];
    const float* bdg = (const float*)d_in[17];
    const float* bdb = (const float*)d_in[18];
    const float* bdm = (const float*)d_in[19];
    const float* bdv = (const float*)d_in[20];
    const float* f2w = (const float*)d_in[21];
    const float* f2b = (const float*)d_in[22];
    float* out = (float*)d_out;

    k_zero<<<(N_NODES + 255) / 256, 256>>>();
    k_deg<<<(N_EDGES + 255) / 256, 256>>>(ei);
    k_dis<<<(N_NODES + 255) / 256, 256>>>();
    k_scan<<<1, 1024>>>();
    k_fill<<<(N_EDGES + 255) / 256, 256>>>(ei);

    k_gemm1<<<(N_NODES * 32 + 255) / 256, 256>>>(x, c1w);
    k_agg1<<<(N_NODES * 32 + 255) / 256, 256>>>(c1b, bn1g, bn1b, bn1m, bn1v);
    k_gemm2<<<((N_NODES / 4) * 32 + 255) / 256, 256>>>(c2w);
    k_agg2<<<(N_NODES * 32 + 255) / 256, 256>>>(c2b, bn2g, bn2b, bn2m, bn2v);
    k_fc1<<<(N_NODES * 32 + 255) / 256, 256>>>(f1w, f1b, bdg, bdb, bdm, bdv);
    k_fc2<<<((N_NODES / 2) * 32 + 255) / 256, 256>>>(f2w, f2b, out);
    k_pool<<<(N_NODES + 511) / 512, 256>>>(bat);
    k_fin<<<(N_GRAPHS * LAT + 255) / 256, 256>>>(out);
}

// round 8
// speedup vs baseline: 1.1530x; 1.1530x over previous
#include <cuda_runtime.h>

#define N_NODES 100000
#define N_EDGES 3200000
#define N_GRAPHS 64
#define IN_CH 64
#define HID 128
#define LAT 32
#define EPS 1e-5f

#define SCAN_BLK 512
#define SCAN_NBLK ((N_NODES + SCAN_BLK - 1) / SCAN_BLK)   // 196

// ---------------- scratch (static device allocations; no runtime allocs) ----------------
__device__ __align__(16) float g_h1[(size_t)N_NODES * HID];   // x @ W1
__device__ __align__(16) float g_a1[(size_t)N_NODES * HID];   // agg1 + bn + relu
__device__ __align__(16) float g_z [(size_t)N_NODES * LAT];   // a1 @ W2
__device__ __align__(16) float g_zn[(size_t)N_NODES * LAT];   // agg2 + bn + relu (z_nodes)
__device__ __align__(16) float g_d [(size_t)N_NODES * HID];   // decoder hidden
__device__ float g_dis[N_NODES];
__device__ int   g_deg[N_NODES];
__device__ int   g_off[N_NODES + 1];
__device__ int   g_cnt[N_NODES];
__device__ int   g_rows[N_EDGES];
__device__ int   g_bsum[SCAN_NBLK];
__device__ float g_zsum[N_GRAPHS * LAT];
__device__ int   g_gcnt[N_GRAPHS];

// ---------------- setup kernels ----------------
__global__ void k_zero() {
    int i = blockIdx.x * blockDim.x + threadIdx.x;
    if (i < N_NODES) { g_deg[i] = 0; g_cnt[i] = 0; }
    if (i < N_GRAPHS * LAT) g_zsum[i] = 0.f;
    if (i < N_GRAPHS) g_gcnt[i] = 0;
}

__global__ void k_deg(const int* __restrict__ ei) {
    int e = blockIdx.x * blockDim.x + threadIdx.x;
    if (e < N_EDGES) {
        int c = ei[N_EDGES + e];
        atomicAdd(&g_deg[c], 1);
    }
}

// ---- multi-block exclusive scan of g_deg -> g_off ----
// phase 1: per-block scan, write block-exclusive partials + block totals
__global__ void k_scan1() {
    __shared__ int ss[SCAN_BLK];
    int tid = threadIdx.x;
    int i = blockIdx.x * SCAN_BLK + tid;
    int v = (i < N_NODES) ? g_deg[i] : 0;
    ss[tid] = v;
    __syncthreads();
    for (int off = 1; off < SCAN_BLK; off <<= 1) {
        int t = (tid >= off) ? ss[tid - off] : 0;
        __syncthreads();
        ss[tid] += t;
        __syncthreads();
    }
    if (i < N_NODES) g_off[i] = ss[tid] - v;           // exclusive within block
    if (tid == SCAN_BLK - 1) g_bsum[blockIdx.x] = ss[tid];
}

// phase 2: single small block scans the block totals (SCAN_NBLK <= 256)
__global__ void k_scan2() {
    __shared__ int ss[256];
    int tid = threadIdx.x;
    int v = (tid < SCAN_NBLK) ? g_bsum[tid] : 0;
    ss[tid] = v;
    __syncthreads();
    for (int off = 1; off < 256; off <<= 1) {
        int t = (tid >= off) ? ss[tid - off] : 0;
        __syncthreads();
        ss[tid] += t;
        __syncthreads();
    }
    if (tid < SCAN_NBLK) g_bsum[tid] = ss[tid] - v;    // exclusive block offsets
    if (tid == 0) g_off[N_NODES] = N_EDGES;
}

// phase 3: uniform add of block offsets, fused with dis = rsqrt(deg)
__global__ void k_scan3() {
    int i = blockIdx.x * blockDim.x + threadIdx.x;
    if (i < N_NODES) {
        g_off[i] += g_bsum[i / SCAN_BLK];
        int d = g_deg[i];
        g_dis[i] = (d > 0) ? rsqrtf((float)d) : 0.f;
    }
}

__global__ void k_fill(const int* __restrict__ ei) {
    int e = blockIdx.x * blockDim.x + threadIdx.x;
    if (e < N_EDGES) {
        int r = ei[e];
        int c = ei[N_EDGES + e];
        int pos = g_off[c] + atomicAdd(&g_cnt[c], 1);
        g_rows[pos] = r;
    }
}

// ---------------- GEMM1: h1 = x[N,64] @ W1[64,128] (warp per node) ----------------
__global__ void k_gemm1(const float* __restrict__ x, const float* __restrict__ w) {
    int warp = (blockIdx.x * blockDim.x + threadIdx.x) >> 5;
    int lane = threadIdx.x & 31;
    if (warp >= N_NODES) return;
    float x0 = x[warp * 64 + lane];
    float x1 = x[warp * 64 + 32 + lane];
    const float4* __restrict__ w4 = (const float4*)w;
    float4 acc = make_float4(0.f, 0.f, 0.f, 0.f);
#pragma unroll 8
    for (int k = 0; k < 32; k++) {
        float xk = __shfl_sync(0xffffffffu, x0, k);
        float4 wv = w4[k * 32 + lane];
        acc.x += xk * wv.x; acc.y += xk * wv.y; acc.z += xk * wv.z; acc.w += xk * wv.w;
    }
#pragma unroll 8
    for (int k = 0; k < 32; k++) {
        float xk = __shfl_sync(0xffffffffu, x1, k);
        float4 wv = w4[(k + 32) * 32 + lane];
        acc.x += xk * wv.x; acc.y += xk * wv.y; acc.z += xk * wv.z; acc.w += xk * wv.w;
    }
    ((float4*)g_h1)[warp * 32 + lane] = acc;
}

// ---------------- agg1: warp per node, 128ch (float4/thread), + bias + bn1 + relu ----------------
__global__ void k_agg1(const float* __restrict__ cb,
                       const float* __restrict__ bg, const float* __restrict__ bb,
                       const float* __restrict__ bm, const float* __restrict__ bv) {
    int node = (blockIdx.x * blockDim.x + threadIdx.x) >> 5;
    int lane = threadIdx.x & 31;
    if (node >= N_NODES) return;
    int s = g_off[node], e = g_off[node + 1];
    const float4* __restrict__ h4 = (const float4*)g_h1;
    float4 acc = make_float4(0.f, 0.f, 0.f, 0.f);
    int i = s;
    for (; i + 3 < e; i += 4) {
        int r0 = g_rows[i], r1 = g_rows[i + 1], r2 = g_rows[i + 2], r3 = g_rows[i + 3];
        float w0 = g_dis[r0], w1 = g_dis[r1], w2 = g_dis[r2], w3 = g_dis[r3];
        float4 v0 = h4[r0 * 32 + lane];
        float4 v1 = h4[r1 * 32 + lane];
        float4 v2 = h4[r2 * 32 + lane];
        float4 v3 = h4[r3 * 32 + lane];
        acc.x += v0.x * w0 + v1.x * w1 + v2.x * w2 + v3.x * w3;
        acc.y += v0.y * w0 + v1.y * w1 + v2.y * w2 + v3.y * w3;
        acc.z += v0.z * w0 + v1.z * w1 + v2.z * w2 + v3.z * w3;
        acc.w += v0.w * w0 + v1.w * w1 + v2.w * w2 + v3.w * w3;
    }
    for (; i < e; i++) {
        int r = g_rows[i];
        float w = g_dis[r];
        float4 v = h4[r * 32 + lane];
        acc.x += v.x * w; acc.y += v.y * w; acc.z += v.z * w; acc.w += v.w * w;
    }
    float dc = g_dis[node];
    int c0 = lane * 4;
    float4 o;
    {
        float v0 = acc.x * dc + cb[c0 + 0];
        float v1 = acc.y * dc + cb[c0 + 1];
        float v2 = acc.z * dc + cb[c0 + 2];
        float v3 = acc.w * dc + cb[c0 + 3];
        v0 = (v0 - bm[c0 + 0]) * bg[c0 + 0] * rsqrtf(bv[c0 + 0] + EPS) + bb[c0 + 0];
        v1 = (v1 - bm[c0 + 1]) * bg[c0 + 1] * rsqrtf(bv[c0 + 1] + EPS) + bb[c0 + 1];
        v2 = (v2 - bm[c0 + 2]) * bg[c0 + 2] * rsqrtf(bv[c0 + 2] + EPS) + bb[c0 + 2];
        v3 = (v3 - bm[c0 + 3]) * bg[c0 + 3] * rsqrtf(bv[c0 + 3] + EPS) + bb[c0 + 3];
        o = make_float4(fmaxf(v0, 0.f), fmaxf(v1, 0.f), fmaxf(v2, 0.f), fmaxf(v3, 0.f));
    }
    ((float4*)g_a1)[node * 32 + lane] = o;
}

// ---------------- GEMM2: z = a1[N,128] @ W2[128,32] (warp per 4 nodes) ----------------
__global__ void k_gemm2(const float* __restrict__ w) {
    int warp = (blockIdx.x * blockDim.x + threadIdx.x) >> 5;
    int lane = threadIdx.x & 31;
    int n0 = warp * 4;
    if (n0 >= N_NODES) return;
    float xv[4][4];
#pragma unroll
    for (int j = 0; j < 4; j++)
#pragma unroll
        for (int q = 0; q < 4; q++)
            xv[j][q] = g_a1[(n0 + j) * 128 + q * 32 + lane];
    float acc[4] = {0.f, 0.f, 0.f, 0.f};
#pragma unroll
    for (int q = 0; q < 4; q++) {
#pragma unroll 8
        for (int k = 0; k < 32; k++) {
            float wv = w[(q * 32 + k) * 32 + lane];
            float a0 = __shfl_sync(0xffffffffu, xv[0][q], k);
            float a1 = __shfl_sync(0xffffffffu, xv[1][q], k);
            float a2 = __shfl_sync(0xffffffffu, xv[2][q], k);
            float a3 = __shfl_sync(0xffffffffu, xv[3][q], k);
            acc[0] += a0 * wv; acc[1] += a1 * wv; acc[2] += a2 * wv; acc[3] += a3 * wv;
        }
    }
#pragma unroll
    for (int j = 0; j < 4; j++)
        g_z[(n0 + j) * 32 + lane] = acc[j];
}

// ---------------- agg2: warp per node, 32ch, + bias + bn2 + relu -> z_nodes ----------------
__global__ void k_agg2(const float* __restrict__ cb,
                       const float* __restrict__ bg, const float* __restrict__ bb,
                       const float* __restrict__ bm, const float* __restrict__ bv) {
    int node = (blockIdx.x * blockDim.x + threadIdx.x) >> 5;
    int lane = threadIdx.x & 31;
    if (node >= N_NODES) return;
    int s = g_off[node], e = g_off[node + 1];
    float acc = 0.f;
    int i = s;
    for (; i + 3 < e; i += 4) {
        int r0 = g_rows[i], r1 = g_rows[i + 1], r2 = g_rows[i + 2], r3 = g_rows[i + 3];
        float w0 = g_dis[r0], w1 = g_dis[r1], w2 = g_dis[r2], w3 = g_dis[r3];
        acc += g_z[r0 * 32 + lane] * w0 + g_z[r1 * 32 + lane] * w1
             + g_z[r2 * 32 + lane] * w2 + g_z[r3 * 32 + lane] * w3;
    }
    for (; i < e; i++) {
        int r = g_rows[i];
        acc += g_z[r * 32 + lane] * g_dis[r];
    }
    float v = acc * g_dis[node] + cb[lane];
    v = (v - bm[lane]) * bg[lane] * rsqrtf(bv[lane] + EPS) + bb[lane];
    g_zn[node * 32 + lane] = fmaxf(v, 0.f);
}

// ---------------- fc1: d = relu(bn(zn[N,32] @ fc1w[32,128] + b)) (warp per node) ----------------
__global__ void k_fc1(const float* __restrict__ w, const float* __restrict__ fb,
                      const float* __restrict__ bg, const float* __restrict__ bb,
                      const float* __restrict__ bm, const float* __restrict__ bv) {
    int node = (blockIdx.x * blockDim.x + threadIdx.x) >> 5;
    int lane = threadIdx.x & 31;
    if (node >= N_NODES) return;
    float xv = g_zn[node * 32 + lane];
    const float4* __restrict__ w4 = (const float4*)w;
    float4 acc = make_float4(0.f, 0.f, 0.f, 0.f);
#pragma unroll 8
    for (int k = 0; k < 32; k++) {
        float xk = __shfl_sync(0xffffffffu, xv, k);
        float4 wv = w4[k * 32 + lane];
        acc.x += xk * wv.x; acc.y += xk * wv.y; acc.z += xk * wv.z; acc.w += xk * wv.w;
    }
    int c0 = lane * 4;
    float v0 = acc.x + fb[c0 + 0];
    float v1 = acc.y + fb[c0 + 1];
    float v2 = acc.z + fb[c0 + 2];
    float v3 = acc.w + fb[c0 + 3];
    v0 = (v0 - bm[c0 + 0]) * bg[c0 + 0] * rsqrtf(bv[c0 + 0] + EPS) + bb[c0 + 0];
    v1 = (v1 - bm[c0 + 1]) * bg[c0 + 1] * rsqrtf(bv[c0 + 1] + EPS) + bb[c0 + 1];
    v2 = (v2 - bm[c0 + 2]) * bg[c0 + 2] * rsqrtf(bv[c0 + 2] + EPS) + bb[c0 + 2];
    v3 = (v3 - bm[c0 + 3]) * bg[c0 + 3] * rsqrtf(bv[c0 + 3] + EPS) + bb[c0 + 3];
    float4 o = make_float4(fmaxf(v0, 0.f), fmaxf(v1, 0.f), fmaxf(v2, 0.f), fmaxf(v3, 0.f));
    ((float4*)g_d)[node * 32 + lane] = o;
}

// ---------------- fc2: x_hat = d[N,128] @ fc2w[128,64] + b (warp per 2 nodes) -> d_out ----------------
__global__ void k_fc2(const float* __restrict__ w, const float* __restrict__ fb,
                      float* __restrict__ out) {
    int warp = (blockIdx.x * blockDim.x + threadIdx.x) >> 5;
    int lane = threadIdx.x & 31;
    int n0 = warp * 2;
    if (n0 >= N_NODES) return;
    float xv0[4], xv1[4];
#pragma unroll
    for (int q = 0; q < 4; q++) {
        xv0[q] = g_d[(size_t)n0 * 128 + q * 32 + lane];
        xv1[q] = g_d[(size_t)(n0 + 1) * 128 + q * 32 + lane];
    }
    const float2* __restrict__ w2 = (const float2*)w;
    float2 acc0 = make_float2(0.f, 0.f);
    float2 acc1 = make_float2(0.f, 0.f);
#pragma unroll
    for (int q = 0; q < 4; q++) {
#pragma unroll 8
        for (int k = 0; k < 32; k++) {
            float2 wv = w2[(q * 32 + k) * 32 + lane];
            float a = __shfl_sync(0xffffffffu, xv0[q], k);
            float b = __shfl_sync(0xffffffffu, xv1[q], k);
            acc0.x += a * wv.x; acc0.y += a * wv.y;
            acc1.x += b * wv.x; acc1.y += b * wv.y;
        }
    }
    int c0 = lane * 2;
    out[(size_t)n0 * 64 + c0 + 0] = acc0.x + fb[c0 + 0];
    out[(size_t)n0 * 64 + c0 + 1] = acc0.y + fb[c0 + 1];
    out[(size_t)(n0 + 1) * 64 + c0 + 0] = acc1.x + fb[c0 + 0];
    out[(size_t)(n0 + 1) * 64 + c0 + 1] = acc1.y + fb[c0 + 1];
}

// ---------------- pooling: smem per-block reduction over sorted batch ----------------
__global__ void k_pool(const int* __restrict__ batch) {
    __shared__ float sacc[N_GRAPHS * LAT];
    __shared__ int scnt[N_GRAPHS];
    int tid = threadIdx.x;
    for (int i = tid; i < N_GRAPHS * LAT; i += blockDim.x) sacc[i] = 0.f;
    if (tid < N_GRAPHS) scnt[tid] = 0;
    __syncthreads();
    const int NPB = 512;
    int base = blockIdx.x * NPB;
    int wid = tid >> 5, lane = tid & 31;
    int lim = base + NPB; if (lim > N_NODES) lim = N_NODES;
    for (int n = base + wid; n < lim; n += 8) {
        int g = batch[n];
        atomicAdd(&sacc[g * 32 + lane], g_zn[n * 32 + lane]);
        if (lane == 0) atomicAdd(&scnt[g], 1);
    }
    __syncthreads();
    for (int i = tid; i < N_GRAPHS * LAT; i += blockDim.x)
        if (sacc[i] != 0.f) atomicAdd(&g_zsum[i], sacc[i]);
    if (tid < N_GRAPHS && scnt[tid] != 0) atomicAdd(&g_gcnt[tid], scnt[tid]);
}

__global__ void k_fin(float* __restrict__ out) {
    int i = blockIdx.x * blockDim.x + threadIdx.x;
    if (i < N_GRAPHS * LAT) {
        int g = i >> 5;
        float c = (float)g_gcnt[g];
        out[(size_t)N_NODES * IN_CH + i] = g_zsum[i] / fmaxf(c, 1.f);
    }
}

// ---------------- launch ----------------
extern "C" void kernel_launch(void* const* d_in, const int* in_sizes, int n_in,
                              void* d_out, int out_size) {
    const float* x   = (const float*)d_in[0];
    const int*   ei  = (const int*)d_in[1];
    const int*   bat = (const int*)d_in[2];
    const float* c1w = (const float*)d_in[3];
    const float* c1b = (const float*)d_in[4];
    const float* c2w = (const float*)d_in[5];
    const float* c2b = (const float*)d_in[6];
    const float* bn1g = (const float*)d_in[7];
    const float* bn1b = (const float*)d_in[8];
    const float* bn1m = (const float*)d_in[9];
    const float* bn1v = (const float*)d_in[10];
    const float* bn2g = (const float*)d_in[11];
    const float* bn2b = (const float*)d_in[12];
    const float* bn2m = (const float*)d_in[13];
    const float* bn2v = (const float*)d_in[14];
    const float* f1w = (const float*)d_in[15];
    const float* f1b = (const float*)d_in[16];
    const float* bdg = (const float*)d_in[17];
    const float* bdb = (const float*)d_in[18];
    const float* bdm = (const float*)d_in[19];
    const float* bdv = (const float*)d_in[20];
    const float* f2w = (const float*)d_in[21];
    const float* f2b = (const float*)d_in[22];
    float* out = (float*)d_out;

    k_zero<<<(N_NODES + 255) / 256, 256>>>();
    k_deg<<<(N_EDGES + 255) / 256, 256>>>(ei);
    k_scan1<<<SCAN_NBLK, SCAN_BLK>>>();
    k_scan2<<<1, 256>>>();
    k_scan3<<<(N_NODES + 255) / 256, 256>>>();
    k_fill<<<(N_EDGES + 255) / 256, 256>>>(ei);

    k_gemm1<<<(N_NODES * 32 + 255) / 256, 256>>>(x, c1w);
    k_agg1<<<(N_NODES * 32 + 255) / 256, 256>>>(c1b, bn1g, bn1b, bn1m, bn1v);
    k_gemm2<<<((N_NODES / 4) * 32 + 255) / 256, 256>>>(c2w);
    k_agg2<<<(N_NODES * 32 + 255) / 256, 256>>>(c2b, bn2g, bn2b, bn2m, bn2v);
    k_fc1<<<(N_NODES * 32 + 255) / 256, 256>>>(f1w, f1b, bdg, bdb, bdm, bdv);
    k_fc2<<<((N_NODES / 2) * 32 + 255) / 256, 256>>>(f2w, f2b, out);
    k_pool<<<(N_NODES + 511) / 512, 256>>>(bat);
    k_fin<<<(N_GRAPHS * LAT + 255) / 256, 256>>>(out);
}